// round 13
// baseline (speedup 1.0000x reference)
#include <cuda_runtime.h>
#include <cstdio>

// Problem constants
#define B_ROWS   65536
#define F_DIM    512
#define H_DIM    256
#define A_DIM    4
#define E_DIM    32

#define SEG_CAP  65568           // per-task segment capacity (multiple of 32)
#define IDX_LEN  (3 * SEG_CAP)   // 196704
#define W_MP_OFF 7680            // Mp[2][5]
#define W_B_OFF  7690            // bias[3][5]
#define W_ME_OFF 7712            // Me[32][5] scratch (not copied to smem)
#define W_TOTAL  7872
#define SMEM_W   7712            // floats copied to shared (7705 used)

#define GRID_MAIN  296           // 148 SMs * 2 blocks
#define WARPS_MAIN (GRID_MAIN * 8)
#define NCH_SEG    2049          // SEG_CAP / 32
#define NCHUNK     (3 * NCH_SEG) // 6147 chunks of 32 rows

// Scratch (no allocations allowed -> device globals; zero-initialized at load)
__device__ float    g_W[W_TOTAL];
__device__ unsigned g_idx[IDX_LEN];   // stores b+1; 0 == empty (never written in tails)
__device__ int      g_cnt[3];         // zeroed by k_main for the NEXT launch
__device__ int      g_work = WARPS_MAIN;  // re-armed by K1 each launch

struct Params {
    const float *features, *pointgoal;
    const float *a0W1, *a0b1, *a0W2, *a0b2;
    const float *a1W1, *a1b1, *a1W2, *a1b2;
    const float *a2Wp, *a2bp, *a2W1, *a2b1, *a2W2, *a2b2;
    const float *c0W1, *c0b1, *c0W2, *c0b2;
    const float *c1W1, *c1b1, *c1W2, *c1b2;
    const float *c2Wp, *c2bp, *c2W1, *c2b1, *c2W2, *c2b2;
    const int   *task;
};

// 256-length dot: v[h] * w2[h*st] (w2 pre-offset by output column)
__device__ __forceinline__ float dot256(const float* __restrict__ vrow,
                                        const float* __restrict__ w2, int st) {
    float a0 = 0.f, a1 = 0.f, a2 = 0.f, a3 = 0.f;
#pragma unroll 8
    for (int h = 0; h < 256; h += 4) {
        float4 v = *reinterpret_cast<const float4*>(vrow + h);
        a0 = fmaf(v.x, w2[(h + 0) * st], a0);
        a1 = fmaf(v.y, w2[(h + 1) * st], a1);
        a2 = fmaf(v.z, w2[(h + 2) * st], a2);
        a3 = fmaf(v.w, w2[(h + 3) * st], a3);
    }
    return (a0 + a1) + (a2 + a3);
}

// ---------------------------------------------------------------------------
// K1 (single prep kernel):
//   blocks [0,256)  : warp-aggregated atomic scatter of rows into fixed-cap
//                     task segments (g_idx stores b+1; tails stay 0 forever)
//   blocks [256,286): fold M = W1@W2 into swizzled layout (7680 entries)
//   block 286       : Me + bias core, then (after sync) Mp + head-2 bias
//                     finalize + g_work re-arm
// ---------------------------------------------------------------------------
__global__ void k_prep(Params p) {
    if (blockIdx.x < 256) {
        int thr = threadIdx.x;
        int b = blockIdx.x * 256 + thr;
        int t = p.task[b];
        int lane = thr & 31;
        unsigned m0 = __ballot_sync(~0u, t == 0);
        unsigned m1 = __ballot_sync(~0u, t == 1);
        unsigned m2 = __ballot_sync(~0u, t == 2);
        unsigned mym = (t == 0) ? m0 : (t == 1) ? m1 : m2;
        int rank = __popc(mym & ((1u << lane) - 1));
        int ldr = __ffs(mym) - 1;
        int base = 0;
        if (lane == ldr) base = atomicAdd(&g_cnt[t], __popc(mym));
        base = __shfl_sync(~0u, base, ldr);
        g_idx[t * SEG_CAP + base + rank] = (unsigned)b + 1u;
    } else if (blockIdx.x < 286) {
        int idx = (blockIdx.x - 256) * 256 + threadIdx.x;  // [0, 7680)
        // folded M[t][f][col]: col 0 = value (critic), cols 1..4 = logits
        int t = idx / 2560;
        int r = idx - t * 2560;
        int f = r / 5, col = r - f * 5;
        const float *W1, *W2; int st, of;
        if (col == 0) {
            W1 = t == 0 ? p.c0W1 : t == 1 ? p.c1W1 : p.c2W1;
            W2 = t == 0 ? p.c0W2 : t == 1 ? p.c1W2 : p.c2W2;
            st = 1; of = 0;
        } else {
            W1 = t == 0 ? p.a0W1 : t == 1 ? p.a1W1 : p.a2W1;
            W2 = t == 0 ? p.a0W2 : t == 1 ? p.a1W2 : p.a2W2;
            st = A_DIM; of = col - 1;
        }
        float v = dot256(W1 + (size_t)f * H_DIM, W2 + of, st);
        // swizzled layout: main kernel's LDS.128 is broadcast/conflict-free
        int j = f >> 5, ss = (f >> 2) & 7, c = f & 3;
        g_W[t * 2560 + ((j * 5 + col) * 8 + ss) * 4 + c] = v;
    } else {
        int i = threadIdx.x;
        if (i < 160) {
            // Me[e][col]: rows 512..543 of head-2 W1 folded with W2
            int e = i / 5, col = i - e * 5;
            const float* W1 = (col == 0) ? p.c2W1 : p.a2W1;
            const float* W2 = (col == 0) ? p.c2W2 : p.a2W2;
            int st = (col == 0) ? 1 : A_DIM, of = (col == 0) ? 0 : col - 1;
            g_W[W_ME_OFF + e * 5 + col] =
                dot256(W1 + (size_t)(512 + e) * H_DIM, W2 + of, st);
        } else if (i < 175) {
            // bias core: b1 @ W2 + b2
            int k = i - 160;
            int t = k / 5, col = k - t * 5;
            const float *b1, *b2, *W2; int st, of;
            if (col == 0) {
                st = 1; of = 0;
                b1 = t == 0 ? p.c0b1 : t == 1 ? p.c1b1 : p.c2b1;
                b2 = t == 0 ? p.c0b2 : t == 1 ? p.c1b2 : p.c2b2;
                W2 = t == 0 ? p.c0W2 : t == 1 ? p.c1W2 : p.c2W2;
            } else {
                st = A_DIM; of = col - 1;
                b1 = t == 0 ? p.a0b1 : t == 1 ? p.a1b1 : p.a2b1;
                b2 = t == 0 ? p.a0b2 : t == 1 ? p.a1b2 : p.a2b2;
                W2 = t == 0 ? p.a0W2 : t == 1 ? p.a1W2 : p.a2W2;
            }
            g_W[W_B_OFF + k] = b2[of] + dot256(b1, W2 + of, st);
        }
        __syncthreads();
        if (i < 10) {
            // Mp[pp][col] = sum_e Wp[pp][e] * Me[e][col]
            int pp = i / 5, col = i - pp * 5;
            const float* Wp = ((col == 0) ? p.c2Wp : p.a2Wp) + pp * E_DIM;
            float acc = 0.f;
#pragma unroll
            for (int e = 0; e < E_DIM; e++) acc += Wp[e] * g_W[W_ME_OFF + e * 5 + col];
            g_W[W_MP_OFF + pp * 5 + col] = acc;
        } else if (i < 15) {
            // head-2 bias += bp @ Me
            int col = i - 10;
            const float* bp = (col == 0) ? p.c2bp : p.a2bp;
            float acc = 0.f;
#pragma unroll
            for (int e = 0; e < E_DIM; e++) acc += bp[e] * g_W[W_ME_OFF + e * 5 + col];
            g_W[W_B_OFF + 10 + col] += acc;
        } else if (i == 20) {
            g_work = WARPS_MAIN;  // re-arm dynamic-chunk counter for k_main
        }
    }
}

// ---------------------------------------------------------------------------
// K2: main — warp = 4 groups of 8 lanes; each group owns 8 rows of one
//     (segment-uniform) task. 8 independent LDG.128 in flight per j-step,
//     one weight LDS.128 shared by 8 rows, 3-step shfl reduction, dynamic
//     32-row-chunk scheduling. Zeroes g_cnt for the next launch.
// ---------------------------------------------------------------------------
__global__ void __launch_bounds__(256, 2) k_main(const float* __restrict__ feat,
                                                 const float* __restrict__ pgoal,
                                                 float* __restrict__ out) {
    if (blockIdx.x == 0 && threadIdx.x == 0) {
        g_cnt[0] = 0; g_cnt[1] = 0; g_cnt[2] = 0;  // for next launch's k_prep
    }
    __shared__ float sw[SMEM_W];
    for (int i = threadIdx.x; i < 7705; i += 256) sw[i] = g_W[i];
    __syncthreads();

    int lane = threadIdx.x & 31;
    int s = lane & 7;                 // feature sub-lane within group
    int q = lane >> 3;                // group index within warp
    int chunk = blockIdx.x * 8 + (threadIdx.x >> 5);

    while (chunk < NCHUNK) {
        int t = (chunk >= 2 * NCH_SEG) ? 2 : (chunk >= NCH_SEG) ? 1 : 0;
        int off = chunk - t * NCH_SEG;
        // each lane reads one of the chunk's 32 slots
        unsigned pk = g_idx[t * SEG_CAP + off * 32 + lane];
        unsigned act = __ballot_sync(~0u, pk != 0u);
        int nxt = NCHUNK;
        if (act == 0u) {                       // empty chunk: grab next, skip
            if (lane == 0) nxt = atomicAdd(&g_work, 1);
            chunk = __shfl_sync(~0u, nxt, 0);
            continue;
        }

        // gather my group's 8 rows (slots q*8 .. q*8+7)
        unsigned r[8]; unsigned vmask = 0;
#pragma unroll
        for (int i = 0; i < 8; i++) {
            unsigned pv = __shfl_sync(~0u, pk, (q << 3) | i);
            r[i] = pv ? pv - 1u : 0u;
            vmask |= (pv != 0u) << i;
        }

        const float* wb = &sw[t * 2560];
        const float* pr[8];
#pragma unroll
        for (int i = 0; i < 8; i++)
            pr[i] = feat + (size_t)r[i] * F_DIM + s * 4;

        float acc[8][5];
#pragma unroll
        for (int i = 0; i < 8; i++)
#pragma unroll
            for (int c = 0; c < 5; c++) acc[i][c] = 0.f;

#pragma unroll 4
        for (int j = 0; j < 16; j++) {
            float4 x[8];
#pragma unroll
            for (int i = 0; i < 8; i++)
                x[i] = *reinterpret_cast<const float4*>(pr[i] + j * 32);
#pragma unroll
            for (int col = 0; col < 5; col++) {
                float4 w = *reinterpret_cast<const float4*>(wb + ((j * 5 + col) * 8 + s) * 4);
#pragma unroll
                for (int i = 0; i < 8; i++)
                    acc[i][col] = fmaf(x[i].x, w.x, fmaf(x[i].y, w.y,
                                  fmaf(x[i].z, w.z, fmaf(x[i].w, w.w, acc[i][col]))));
            }
        }

        // grab next chunk early so ATOMG latency hides under the reduction
        if (lane == 0) nxt = atomicAdd(&g_work, 1);

        // reduce across the 8 lanes of each group (xor 4,2,1 stays in-group)
#pragma unroll
        for (int i = 0; i < 8; i++)
#pragma unroll
            for (int c = 0; c < 5; c++) {
                float v = acc[i][c];
                v += __shfl_xor_sync(0xffffffffu, v, 4);
                v += __shfl_xor_sync(0xffffffffu, v, 2);
                v += __shfl_xor_sync(0xffffffffu, v, 1);
                acc[i][c] = v;
            }

        if (s == 0) {
#pragma unroll
            for (int i = 0; i < 8; i++) {
                if (!((vmask >> i) & 1u)) continue;
                unsigned row = r[i];
                float o[5];
#pragma unroll
                for (int c = 0; c < 5; c++) o[c] = acc[i][c] + sw[W_B_OFF + t * 5 + c];
                if (t == 2) {
                    float2 g = *reinterpret_cast<const float2*>(pgoal + (size_t)row * 2);
#pragma unroll
                    for (int c = 0; c < 5; c++)
                        o[c] = fmaf(g.x, sw[W_MP_OFF + c], fmaf(g.y, sw[W_MP_OFF + 5 + c], o[c]));
                }
                float* op = out + (size_t)row * 5;
                op[0] = o[0]; op[1] = o[1]; op[2] = o[2]; op[3] = o[3]; op[4] = o[4];
            }
        }

        chunk = __shfl_sync(0xffffffffu, nxt, 0);
    }
}

// ---------------------------------------------------------------------------
extern "C" void kernel_launch(void* const* d_in, const int* in_sizes, int n_in,
                              void* d_out, int out_size) {
    (void)in_sizes; (void)n_in; (void)out_size;
    Params p;
    p.features  = (const float*)d_in[0];
    p.pointgoal = (const float*)d_in[1];
    p.a0W1 = (const float*)d_in[2];  p.a0b1 = (const float*)d_in[3];
    p.a0W2 = (const float*)d_in[4];  p.a0b2 = (const float*)d_in[5];
    p.a1W1 = (const float*)d_in[6];  p.a1b1 = (const float*)d_in[7];
    p.a1W2 = (const float*)d_in[8];  p.a1b2 = (const float*)d_in[9];
    p.a2Wp = (const float*)d_in[10]; p.a2bp = (const float*)d_in[11];
    p.a2W1 = (const float*)d_in[12]; p.a2b1 = (const float*)d_in[13];
    p.a2W2 = (const float*)d_in[14]; p.a2b2 = (const float*)d_in[15];
    p.c0W1 = (const float*)d_in[16]; p.c0b1 = (const float*)d_in[17];
    p.c0W2 = (const float*)d_in[18]; p.c0b2 = (const float*)d_in[19];
    p.c1W1 = (const float*)d_in[20]; p.c1b1 = (const float*)d_in[21];
    p.c1W2 = (const float*)d_in[22]; p.c1b2 = (const float*)d_in[23];
    p.c2Wp = (const float*)d_in[24]; p.c2bp = (const float*)d_in[25];
    p.c2W1 = (const float*)d_in[26]; p.c2b1 = (const float*)d_in[27];
    p.c2W2 = (const float*)d_in[28]; p.c2b2 = (const float*)d_in[29];
    p.task = (const int*)d_in[30];

    k_prep<<<287, 256>>>(p);                   // scatter + folds + bias (one kernel)
    k_main<<<GRID_MAIN, 256>>>(p.features, p.pointgoal, (float*)d_out);
}

// round 17
// speedup vs baseline: 1.1328x; 1.1328x over previous
#include <cuda_runtime.h>
#include <cstdint>
#include <cstdio>

// Problem constants
#define B_ROWS   65536
#define F_DIM    512
#define H_DIM    256
#define A_DIM    4
#define E_DIM    32

#define SEG_CAP  65568           // per-task segment capacity
#define IDX_LEN  (3 * SEG_CAP)
#define W_MP_OFF 7680            // Mp[2][5]
#define W_B_OFF  7690            // bias[3][5]
#define W_ME_OFF 7712            // Me[32][5] scratch (not copied to smem)
#define W_TOTAL  7872

#define GRID_MAIN   148
#define BLK_MAIN    128          // warp0 producer, warps 1-3 consumers
#define STAGE_ROWS  48
#define ROW_BYTES   2048         // 512 floats
#define STAGE_BYTES (STAGE_ROWS * ROW_BYTES)   // 98304
#define DEPTH       2
#define STOPW       0xFFFFFFFFu

// dynamic smem layout
#define OFF_W      (DEPTH * STAGE_BYTES)       // 196608: weights (7712 floats)
#define OFF_META   (OFF_W + 7712 * 4)          // 227456: 2 slots x 52 uints
#define META_STRIDE 52
#define OFF_BAR    (OFF_META + DEPTH * META_STRIDE * 4)  // 227872
#define SMEM_TOTAL (OFF_BAR + 32)              // 227904

// Scratch (no allocations allowed -> device globals; zero-initialized at load)
__device__ float    g_W[W_TOTAL];
__device__ unsigned g_idx[IDX_LEN];   // stores b+1; 0 == empty (tails never written)
__device__ int      g_cnt[3];         // zeroed by k_mid each launch
__device__ int      g_nch[3];         // chunk-count prefix (by k_mid)
__device__ int      g_work;           // dynamic chunk counter (reset by k_mid)

struct Params {
    const float *features, *pointgoal;
    const float *a0W1, *a0b1, *a0W2, *a0b2;
    const float *a1W1, *a1b1, *a1W2, *a1b2;
    const float *a2Wp, *a2bp, *a2W1, *a2b1, *a2W2, *a2b2;
    const float *c0W1, *c0b1, *c0W2, *c0b2;
    const float *c1W1, *c1b1, *c1W2, *c1b2;
    const float *c2Wp, *c2bp, *c2W1, *c2b1, *c2W2, *c2b2;
    const int   *task;
};

// ---- mbarrier / TMA helpers -----------------------------------------------
__device__ __forceinline__ void mbar_init(uint32_t a, uint32_t cnt) {
    asm volatile("mbarrier.init.shared.b64 [%0], %1;" :: "r"(a), "r"(cnt) : "memory");
}
__device__ __forceinline__ void mbar_arrive(uint32_t a) {
    asm volatile("mbarrier.arrive.shared.b64 _, [%0];" :: "r"(a) : "memory");
}
__device__ __forceinline__ void mbar_expect_tx(uint32_t a, uint32_t bytes) {
    asm volatile("mbarrier.arrive.expect_tx.shared.b64 _, [%0], %1;"
                 :: "r"(a), "r"(bytes) : "memory");
}
__device__ __forceinline__ void mbar_wait(uint32_t a, uint32_t parity) {
    asm volatile(
        "{\n\t.reg .pred P;\n\t"
        "W%=:\n\t"
        "mbarrier.try_wait.parity.acquire.cta.shared::cta.b64 P, [%0], %1, 0x989680;\n\t"
        "@!P bra W%=;\n\t}"
        :: "r"(a), "r"(parity) : "memory");
}
__device__ __forceinline__ void bulk_g2s(uint32_t dst, const void* src,
                                         uint32_t bytes, uint32_t mbar) {
    asm volatile(
        "cp.async.bulk.shared::cta.global.mbarrier::complete_tx::bytes [%0], [%1], %2, [%3];"
        :: "r"(dst), "l"(__cvta_generic_to_global(src)), "r"(bytes), "r"(mbar)
        : "memory");
}

// 256-length dot: v[h] * w2[h*st] (w2 pre-offset by output column)
__device__ __forceinline__ float dot256(const float* __restrict__ vrow,
                                        const float* __restrict__ w2, int st) {
    float a0 = 0.f, a1 = 0.f, a2 = 0.f, a3 = 0.f;
#pragma unroll 8
    for (int h = 0; h < 256; h += 4) {
        float4 v = *reinterpret_cast<const float4*>(vrow + h);
        a0 = fmaf(v.x, w2[(h + 0) * st], a0);
        a1 = fmaf(v.y, w2[(h + 1) * st], a1);
        a2 = fmaf(v.z, w2[(h + 2) * st], a2);
        a3 = fmaf(v.w, w2[(h + 3) * st], a3);
    }
    return (a0 + a1) + (a2 + a3);
}

// ---------------------------------------------------------------------------
// K1: blocks [0,256): warp-aggregated atomic scatter into fixed-cap segments
//     blocks [256,286): fold M = W1@W2 (swizzled);  block 286: Me + bias + Mp
// ---------------------------------------------------------------------------
__global__ void k_prep(Params p) {
    if (blockIdx.x < 256) {
        int thr = threadIdx.x;
        int b = blockIdx.x * 256 + thr;
        int t = p.task[b];
        int lane = thr & 31;
        unsigned m0 = __ballot_sync(~0u, t == 0);
        unsigned m1 = __ballot_sync(~0u, t == 1);
        unsigned m2 = __ballot_sync(~0u, t == 2);
        unsigned mym = (t == 0) ? m0 : (t == 1) ? m1 : m2;
        int rank = __popc(mym & ((1u << lane) - 1));
        int ldr = __ffs(mym) - 1;
        int base = 0;
        if (lane == ldr) base = atomicAdd(&g_cnt[t], __popc(mym));
        base = __shfl_sync(~0u, base, ldr);
        g_idx[t * SEG_CAP + base + rank] = (unsigned)b + 1u;
    } else if (blockIdx.x < 286) {
        int idx = (blockIdx.x - 256) * 256 + threadIdx.x;  // [0, 7680)
        int t = idx / 2560;
        int r = idx - t * 2560;
        int f = r / 5, col = r - f * 5;
        const float *W1, *W2; int st, of;
        if (col == 0) {
            W1 = t == 0 ? p.c0W1 : t == 1 ? p.c1W1 : p.c2W1;
            W2 = t == 0 ? p.c0W2 : t == 1 ? p.c1W2 : p.c2W2;
            st = 1; of = 0;
        } else {
            W1 = t == 0 ? p.a0W1 : t == 1 ? p.a1W1 : p.a2W1;
            W2 = t == 0 ? p.a0W2 : t == 1 ? p.a1W2 : p.a2W2;
            st = A_DIM; of = col - 1;
        }
        float v = dot256(W1 + (size_t)f * H_DIM, W2 + of, st);
        int j = f >> 5, ss = (f >> 2) & 7, c = f & 3;
        g_W[t * 2560 + ((j * 5 + col) * 8 + ss) * 4 + c] = v;
    } else {
        int i = threadIdx.x;
        if (i < 160) {
            int e = i / 5, col = i - e * 5;
            const float* W1 = (col == 0) ? p.c2W1 : p.a2W1;
            const float* W2 = (col == 0) ? p.c2W2 : p.a2W2;
            int st = (col == 0) ? 1 : A_DIM, of = (col == 0) ? 0 : col - 1;
            g_W[W_ME_OFF + e * 5 + col] =
                dot256(W1 + (size_t)(512 + e) * H_DIM, W2 + of, st);
        } else if (i < 175) {
            int k = i - 160;
            int t = k / 5, col = k - t * 5;
            const float *b1, *b2, *W2; int st, of;
            if (col == 0) {
                st = 1; of = 0;
                b1 = t == 0 ? p.c0b1 : t == 1 ? p.c1b1 : p.c2b1;
                b2 = t == 0 ? p.c0b2 : t == 1 ? p.c1b2 : p.c2b2;
                W2 = t == 0 ? p.c0W2 : t == 1 ? p.c1W2 : p.c2W2;
            } else {
                st = A_DIM; of = col - 1;
                b1 = t == 0 ? p.a0b1 : t == 1 ? p.a1b1 : p.a2b1;
                b2 = t == 0 ? p.a0b2 : t == 1 ? p.a1b2 : p.a2b2;
                W2 = t == 0 ? p.a0W2 : t == 1 ? p.a1W2 : p.a2W2;
            }
            g_W[W_B_OFF + k] = b2[of] + dot256(b1, W2 + of, st);
        }
        __syncthreads();
        if (i < 10) {
            int pp = i / 5, col = i - pp * 5;
            const float* Wp = ((col == 0) ? p.c2Wp : p.a2Wp) + pp * E_DIM;
            float acc = 0.f;
#pragma unroll
            for (int e = 0; e < E_DIM; e++) acc += Wp[e] * g_W[W_ME_OFF + e * 5 + col];
            g_W[W_MP_OFF + pp * 5 + col] = acc;
        } else if (i < 15) {
            int col = i - 10;
            const float* bp = (col == 0) ? p.c2bp : p.a2bp;
            float acc = 0.f;
#pragma unroll
            for (int e = 0; e < E_DIM; e++) acc += bp[e] * g_W[W_ME_OFF + e * 5 + col];
            g_W[W_B_OFF + 10 + col] += acc;
        }
    }
}

// ---------------------------------------------------------------------------
// K2 (tiny): exact chunk counts from scatter totals; reset counters.
// ---------------------------------------------------------------------------
__global__ void k_mid() {
    if (threadIdx.x == 0) {
        int n0 = (g_cnt[0] + STAGE_ROWS - 1) / STAGE_ROWS;
        int n1 = (g_cnt[1] + STAGE_ROWS - 1) / STAGE_ROWS;
        int n2 = (g_cnt[2] + STAGE_ROWS - 1) / STAGE_ROWS;
        g_nch[0] = n0;
        g_nch[1] = n0 + n1;
        g_nch[2] = n0 + n1 + n2;
        g_work = 0;
        g_cnt[0] = 0; g_cnt[1] = 0; g_cnt[2] = 0;  // for next launch's prep
    }
}

// ---------------------------------------------------------------------------
// K3: main — TMA-fed producer/consumer pipeline.
//   warp 0: claims 48-row chunks, gathers rows via per-row 2KB cp.async.bulk
//           into a double-buffered smem stage, publishes meta, arms mbarrier.
//   warps 1-3: 16 rows each (R8 layout: 4 groups x 8 lanes x 4 rows),
//           broadcast weight LDS, 3-step shfl reduce, epilogue store.
// ---------------------------------------------------------------------------
__global__ void __launch_bounds__(BLK_MAIN, 1) k_main(const float* __restrict__ feat,
                                                      const float* __restrict__ pgoal,
                                                      float* __restrict__ out) {
    extern __shared__ __align__(16) char smem[];
    float* sw = reinterpret_cast<float*>(smem + OFF_W);
    unsigned* smeta = reinterpret_cast<unsigned*>(smem + OFF_META);
    uint32_t sbase = (uint32_t)__cvta_generic_to_shared(smem);
    uint32_t bar_full0 = sbase + OFF_BAR;
    uint32_t bar_empty0 = sbase + OFF_BAR + 16;

    int tid = threadIdx.x;
    int wid = tid >> 5;
    int lane = tid & 31;

    // weights -> smem (16B vector copies)
    {
        const uint4* src = reinterpret_cast<const uint4*>(g_W);
        uint4* dst = reinterpret_cast<uint4*>(sw);
        for (int i = tid; i < 7712 / 4; i += BLK_MAIN) dst[i] = src[i];
    }
    if (tid == 0) {
#pragma unroll
        for (int d = 0; d < DEPTH; d++) {
            mbar_init(bar_full0 + d * 8, 32);            // producer lanes + tx
            mbar_init(bar_empty0 + d * 8, BLK_MAIN - 32); // consumer threads
        }
    }
    __syncthreads();

    const int n0 = g_nch[0], n01 = g_nch[1], nch = g_nch[2];

    // ---- producer refill lambda (warp 0 only) ----
    auto refill = [&](int slot, int id) {
        int t = (id < n0) ? 0 : (id < n01) ? 1 : 2;
        int off = id - ((t == 0) ? 0 : (t == 1) ? n0 : n01);
        int base = t * SEG_CAP + off * STAGE_ROWS;
        unsigned pkA = g_idx[base + lane];
        unsigned pkB = (lane < 16) ? g_idx[base + 32 + lane] : 0u;
        int nv = __popc(__ballot_sync(~0u, pkA != 0u)) +
                 __popc(__ballot_sync(~0u, pkB != 0u));
        smeta[slot * META_STRIDE + lane] = pkA;
        if (lane < 16) smeta[slot * META_STRIDE + 32 + lane] = pkB;
        if (lane == 0) smeta[slot * META_STRIDE + 48] = (unsigned)t;
        uint32_t mb = bar_full0 + slot * 8;
        if (lane == 0) mbar_expect_tx(mb, (uint32_t)nv * ROW_BYTES);
        uint32_t dstb = sbase + slot * STAGE_BYTES;
        if (pkA) bulk_g2s(dstb + lane * ROW_BYTES,
                          feat + (size_t)(pkA - 1u) * F_DIM, ROW_BYTES, mb);
        if (lane < 16 && pkB) bulk_g2s(dstb + (32 + lane) * ROW_BYTES,
                          feat + (size_t)(pkB - 1u) * F_DIM, ROW_BYTES, mb);
        if (lane != 0) mbar_arrive(mb);
    };
    auto refill_stop = [&](int slot) {
        if (lane == 0) smeta[slot * META_STRIDE] = STOPW;
        mbar_arrive(bar_full0 + slot * 8);  // 32 arrivals, 0 tx
    };

    bool prod_done = false;
    if (wid == 0) {
        // prologue: fill both slots
#pragma unroll
        for (int d = 0; d < DEPTH; d++) {
            int id = 0;
            if (lane == 0) id = atomicAdd(&g_work, 1);
            id = __shfl_sync(~0u, id, 0);
            if (!prod_done && id < nch) refill(d, id);
            else { refill_stop(d); prod_done = true; }
        }
    }

    int s8 = lane & 7;      // feature sub-lane within 8-lane group
    int q = lane >> 3;      // group (row-quad) within consumer warp

    for (int i = 0; ; i++) {
        int slot = i & 1;
        uint32_t par = (i >> 1) & 1;
        mbar_wait(bar_full0 + slot * 8, par);

        unsigned w0 = smeta[slot * META_STRIDE];
        if (w0 == STOPW) break;

        if (wid != 0) {
            int t = (int)smeta[slot * META_STRIDE + 48];
            int rb = (wid - 1) * 16 + q * 4;     // this group's 4 rows in stage
            unsigned pk[4];
#pragma unroll
            for (int k = 0; k < 4; k++) pk[k] = smeta[slot * META_STRIDE + rb + k];

            const float* srow = reinterpret_cast<const float*>(smem + slot * STAGE_BYTES);
            const float* wb = &sw[t * 2560];
            const float* f0 = srow + (size_t)(rb + 0) * F_DIM + s8 * 4;
            const float* f1 = srow + (size_t)(rb + 1) * F_DIM + s8 * 4;
            const float* f2 = srow + (size_t)(rb + 2) * F_DIM + s8 * 4;
            const float* f3 = srow + (size_t)(rb + 3) * F_DIM + s8 * 4;

            float acc[4][5];
#pragma unroll
            for (int k = 0; k < 4; k++)
#pragma unroll
                for (int c = 0; c < 5; c++) acc[k][c] = 0.f;

#pragma unroll 4
            for (int j = 0; j < 16; j++) {
                float4 x0 = *reinterpret_cast<const float4*>(f0 + j * 32);
                float4 x1 = *reinterpret_cast<const float4*>(f1 + j * 32);
                float4 x2 = *reinterpret_cast<const float4*>(f2 + j * 32);
                float4 x3 = *reinterpret_cast<const float4*>(f3 + j * 32);
#pragma unroll
                for (int col = 0; col < 5; col++) {
                    float4 w = *reinterpret_cast<const float4*>(wb + ((j * 5 + col) * 8 + s8) * 4);
                    acc[0][col] = fmaf(x0.x, w.x, fmaf(x0.y, w.y, fmaf(x0.z, w.z, fmaf(x0.w, w.w, acc[0][col]))));
                    acc[1][col] = fmaf(x1.x, w.x, fmaf(x1.y, w.y, fmaf(x1.z, w.z, fmaf(x1.w, w.w, acc[1][col]))));
                    acc[2][col] = fmaf(x2.x, w.x, fmaf(x2.y, w.y, fmaf(x2.z, w.z, fmaf(x2.w, w.w, acc[2][col]))));
                    acc[3][col] = fmaf(x3.x, w.x, fmaf(x3.y, w.y, fmaf(x3.z, w.z, fmaf(x3.w, w.w, acc[3][col]))));
                }
            }

#pragma unroll
            for (int k = 0; k < 4; k++)
#pragma unroll
                for (int c = 0; c < 5; c++) {
                    float v = acc[k][c];
                    v += __shfl_xor_sync(0xffffffffu, v, 4);
                    v += __shfl_xor_sync(0xffffffffu, v, 2);
                    v += __shfl_xor_sync(0xffffffffu, v, 1);
                    acc[k][c] = v;
                }

            if (s8 == 0) {
#pragma unroll
                for (int k = 0; k < 4; k++) {
                    if (pk[k] == 0u) continue;
                    unsigned row = pk[k] - 1u;
                    float o[5];
#pragma unroll
                    for (int c = 0; c < 5; c++) o[c] = acc[k][c] + sw[W_B_OFF + t * 5 + c];
                    if (t == 2) {
                        float2 g = *reinterpret_cast<const float2*>(pgoal + (size_t)row * 2);
#pragma unroll
                        for (int c = 0; c < 5; c++)
                            o[c] = fmaf(g.x, sw[W_MP_OFF + c], fmaf(g.y, sw[W_MP_OFF + 5 + c], o[c]));
                    }
                    float* op = out + (size_t)row * 5;
                    op[0] = o[0]; op[1] = o[1]; op[2] = o[2]; op[3] = o[3]; op[4] = o[4];
                }
            }
            mbar_arrive(bar_empty0 + slot * 8);
        } else {
            // producer: once consumers drained this slot, refill it
            if (!prod_done) {
                mbar_wait(bar_empty0 + slot * 8, par);
                int id = 0;
                if (lane == 0) id = atomicAdd(&g_work, 1);
                id = __shfl_sync(~0u, id, 0);
                if (id < nch) refill(slot, id);
                else { refill_stop(slot); prod_done = true; }
            }
        }
    }
}

// ---------------------------------------------------------------------------
extern "C" void kernel_launch(void* const* d_in, const int* in_sizes, int n_in,
                              void* d_out, int out_size) {
    (void)in_sizes; (void)n_in; (void)out_size;
    Params p;
    p.features  = (const float*)d_in[0];
    p.pointgoal = (const float*)d_in[1];
    p.a0W1 = (const float*)d_in[2];  p.a0b1 = (const float*)d_in[3];
    p.a0W2 = (const float*)d_in[4];  p.a0b2 = (const float*)d_in[5];
    p.a1W1 = (const float*)d_in[6];  p.a1b1 = (const float*)d_in[7];
    p.a1W2 = (const float*)d_in[8];  p.a1b2 = (const float*)d_in[9];
    p.a2Wp = (const float*)d_in[10]; p.a2bp = (const float*)d_in[11];
    p.a2W1 = (const float*)d_in[12]; p.a2b1 = (const float*)d_in[13];
    p.a2W2 = (const float*)d_in[14]; p.a2b2 = (const float*)d_in[15];
    p.c0W1 = (const float*)d_in[16]; p.c0b1 = (const float*)d_in[17];
    p.c0W2 = (const float*)d_in[18]; p.c0b2 = (const float*)d_in[19];
    p.c1W1 = (const float*)d_in[20]; p.c1b1 = (const float*)d_in[21];
    p.c1W2 = (const float*)d_in[22]; p.c1b2 = (const float*)d_in[23];
    p.c2Wp = (const float*)d_in[24]; p.c2bp = (const float*)d_in[25];
    p.c2W1 = (const float*)d_in[26]; p.c2b1 = (const float*)d_in[27];
    p.c2W2 = (const float*)d_in[28]; p.c2b2 = (const float*)d_in[29];
    p.task = (const int*)d_in[30];

    static bool attr_done = false;
    if (!attr_done) {
        cudaFuncSetAttribute(k_main, cudaFuncAttributeMaxDynamicSharedMemorySize,
                             SMEM_TOTAL);
        attr_done = true;
    }

    k_prep<<<287, 256>>>(p);                       // scatter + folds + bias
    k_mid<<<1, 32>>>();                            // chunk counts + counter reset
    k_main<<<GRID_MAIN, BLK_MAIN, SMEM_TOTAL>>>(p.features, p.pointgoal,
                                                (float*)d_out);
}